// round 3
// baseline (speedup 1.0000x reference)
#include <cuda_runtime.h>
#include <cstdint>

#define NNODES 50000
#define NEDGES 1600000
#define DFEAT  128
#define HID1   64
#define HID2   128
#define NCLS   40

// ---------------- scratch (static device globals; no runtime alloc) ----------
__device__ __align__(16) float g_h1  [(size_t)NNODES * HID1];
__device__ __align__(16) float g_agg1[(size_t)NNODES * HID1];
__device__ __align__(16) float g_h2  [(size_t)NNODES * HID2];
__device__ __align__(16) float g_agg2[(size_t)NNODES * HID2];
__device__ int   g_deg [NNODES];
__device__ float g_dinv[NNODES];
__device__ float g_dinv2[NNODES];
__device__ float g_norm[NEDGES];

// ---------------- threefry2x32 (bit-exact JAX replica) -----------------------
__host__ __device__ __forceinline__ void threefry2x32(
    uint32_t k0, uint32_t k1, uint32_t x0, uint32_t x1,
    uint32_t& o0, uint32_t& o1) {
  uint32_t ks0 = k0, ks1 = k1, ks2 = k0 ^ k1 ^ 0x1BD11BDAu;
  x0 += ks0; x1 += ks1;
#define TF_ROT(v, d) (((v) << (d)) | ((v) >> (32 - (d))))
#define TF_RND(r) { x0 += x1; x1 = TF_ROT(x1, r); x1 ^= x0; }
  TF_RND(13) TF_RND(15) TF_RND(26) TF_RND(6)
  x0 += ks1; x1 += ks2 + 1u;
  TF_RND(17) TF_RND(29) TF_RND(16) TF_RND(24)
  x0 += ks2; x1 += ks0 + 2u;
  TF_RND(13) TF_RND(15) TF_RND(26) TF_RND(6)
  x0 += ks0; x1 += ks1 + 3u;
  TF_RND(17) TF_RND(29) TF_RND(16) TF_RND(24)
  x0 += ks1; x1 += ks2 + 4u;
  TF_RND(13) TF_RND(15) TF_RND(26) TF_RND(6)
  x0 += ks2; x1 += ks0 + 5u;
#undef TF_RND
#undef TF_ROT
  o0 = x0; o1 = x1;
}

// ---------------- degree / norm kernels --------------------------------------
__global__ void zero_deg_kernel() {
  int i = blockIdx.x * blockDim.x + threadIdx.x;
  if (i < NNODES) g_deg[i] = 0;
}

__global__ void deg_count_kernel(const int* __restrict__ eidx) {
  int e = blockIdx.x * blockDim.x + threadIdx.x;
  if (e < NEDGES) {
    unsigned d = (unsigned)eidx[NEDGES + e];
    if (d < NNODES) atomicAdd(&g_deg[d], 1);
  }
}

__global__ void calc_dinv_kernel() {
  int i = blockIdx.x * blockDim.x + threadIdx.x;
  if (i < NNODES) {
    float d = (float)(g_deg[i] + 1);
    float di = rsqrtf(d);
    g_dinv[i]  = di;
    g_dinv2[i] = di * di;
  }
}

__global__ void edge_norm_kernel(const int* __restrict__ eidx) {
  int e = blockIdx.x * blockDim.x + threadIdx.x;
  if (e < NEDGES) {
    unsigned s = (unsigned)eidx[e];
    unsigned d = (unsigned)eidx[NEDGES + e];
    float n = 0.0f;
    if (s < NNODES && d < NNODES) n = g_dinv[s] * g_dinv[d];
    g_norm[e] = n;
  }
}

// ---------------- generic smem-tiled GEMM: out[r,c] = A[r,:K] @ W[:K,c] (+bias)
template <int K, int NC, int RPB>
__global__ void gemm_kernel(const float* __restrict__ A,
                            const float* __restrict__ W,
                            const float* __restrict__ bias,
                            float* __restrict__ out, int nrows) {
  __shared__ float Ws[K * NC];
  __shared__ float As[RPB * K];
  const int tid = threadIdx.x;
  const int nt = NC * RPB;
  for (int i = tid; i < K * NC; i += nt) Ws[i] = W[i];
  const long row0 = (long)blockIdx.x * RPB;
  for (int i = tid; i < RPB * K; i += nt) {
    long r = row0 + i / K;
    As[i] = (r < nrows) ? A[r * K + (i % K)] : 0.0f;
  }
  __syncthreads();
  const int c = tid % NC;
  const int r = tid / NC;
  float acc = bias ? bias[c] : 0.0f;
  const float* as = &As[r * K];
#pragma unroll 16
  for (int k = 0; k < K; k++) acc = fmaf(as[k], Ws[k * NC + c], acc);
  long gr = row0 + r;
  if (gr < nrows) out[gr * NC + c] = acc;
}

// ---------------- agg init: agg = h * dinv2[row] (self-loop term) ------------
template <int H>
__global__ void init_agg_kernel(const float* __restrict__ h,
                                float* __restrict__ agg) {
  long i4 = (long)blockIdx.x * blockDim.x + threadIdx.x;
  const long total4 = (long)NNODES * H / 4;
  if (i4 >= total4) return;
  long row = (i4 * 4) / H;
  float s = g_dinv2[row];
  float4 v = ((const float4*)h)[i4];
  v.x *= s; v.y *= s; v.z *= s; v.w *= s;
  ((float4*)agg)[i4] = v;
}

// ---------------- edge scatter: agg[dst] += h[src] * norm[e] -----------------
template <int H>
__global__ void scatter_kernel(const int* __restrict__ eidx,
                               const float* __restrict__ h,
                               float* __restrict__ agg) {
  constexpr int CH = H / 16;       // 16-float chunks per edge (4 or 8)
  constexpr int SH = (CH == 4) ? 2 : 3;
  long t = (long)blockIdx.x * blockDim.x + threadIdx.x;
  const long total = (long)NEDGES * CH;
  if (t >= total) return;
  int  chunk = (int)(t & (CH - 1));
  long e = t >> SH;
  unsigned s = (unsigned)eidx[e];
  unsigned d = (unsigned)eidx[NEDGES + e];
  if (s >= NNODES || d >= NNODES) return;
  float norm = g_norm[e];
  const float4* hp = (const float4*)(h + (long)s * H + chunk * 16);
  float* ap = agg + (long)d * H + chunk * 16;
#pragma unroll
  for (int i = 0; i < 4; i++) {
    float4 v = hp[i];
    v.x *= norm; v.y *= norm; v.z *= norm; v.w *= norm;
    asm volatile("red.global.add.v4.f32 [%0], {%1, %2, %3, %4};"
                 :: "l"(ap + i * 4), "f"(v.x), "f"(v.y), "f"(v.z), "f"(v.w)
                 : "memory");
  }
}

// ---------------- epilogue: out = dropout(tanh(agg + bias)) ------------------
// JAX threefry_partitionable random_bits(32): for flat index i,
//   bits[i] = o0 ^ o1 where (o0, o1) = threefry2x32(key, hi32(i), lo32(i)).
// Our sizes < 2^32 so hi = 0.
template <int H>
__global__ void combine_drop_kernel(const float* __restrict__ agg,
                                    const float* __restrict__ bias,
                                    float* __restrict__ out,
                                    uint32_t k0, uint32_t k1) {
  const int total = NNODES * H;
  int i = blockIdx.x * blockDim.x + threadIdx.x;
  if (i >= total) return;
  uint32_t o0, o1;
  threefry2x32(k0, k1, 0u, (uint32_t)i, o0, o1);
  uint32_t bits = o0 ^ o1;
  float t = tanhf(agg[i] + bias[i & (H - 1)]);
  float u = __uint_as_float((bits >> 9) | 0x3f800000u) - 1.0f;
  out[i] = (u < 0.7f) ? (t / 0.7f) : 0.0f;
}

// ---------------- launch ------------------------------------------------------
extern "C" void kernel_launch(void* const* d_in, const int* in_sizes, int n_in,
                              void* d_out, int out_size) {
  const float* x  = (const float*)d_in[0];
  const int*   ei = (const int*)d_in[1];  // int32 [2, E] (JAX x64 disabled)
  const float* W1 = (const float*)d_in[2];
  const float* b1 = (const float*)d_in[3];
  const float* W2 = (const float*)d_in[4];
  const float* b2 = (const float*)d_in[5];
  const float* Wl = (const float*)d_in[6];
  const float* bl = (const float*)d_in[7];
  float* out = (float*)d_out;

  // JAX split(key(42)) with threefry_partitionable (foldlike):
  //   dk_i = threefry(key, (0, i)), both outputs form the new key.
  uint32_t a0, a1, c0, c1;
  threefry2x32(0u, 42u, 0u, 0u, a0, a1);  // dk1 = (a0, a1)
  threefry2x32(0u, 42u, 0u, 1u, c0, c1);  // dk2 = (c0, c1)

  float *p_h1, *p_agg1, *p_h2, *p_agg2;
  cudaGetSymbolAddress((void**)&p_h1,   g_h1);
  cudaGetSymbolAddress((void**)&p_agg1, g_agg1);
  cudaGetSymbolAddress((void**)&p_h2,   g_h2);
  cudaGetSymbolAddress((void**)&p_agg2, g_agg2);

  // degrees + per-edge norms
  zero_deg_kernel  <<<(NNODES + 255) / 256, 256>>>();
  deg_count_kernel <<<(NEDGES + 255) / 256, 256>>>(ei);
  calc_dinv_kernel <<<(NNODES + 255) / 256, 256>>>();
  edge_norm_kernel <<<(NEDGES + 255) / 256, 256>>>(ei);

  // ---- layer 1: h1 = x @ W1 ; agg1 = scatter + self ; h1 = drop(tanh(agg1+b1))
  gemm_kernel<DFEAT, HID1, 16><<<(NNODES + 15) / 16, HID1 * 16>>>(
      x, W1, nullptr, p_h1, NNODES);
  {
    long total4 = (long)NNODES * HID1 / 4;
    init_agg_kernel<HID1><<<(unsigned)((total4 + 255) / 256), 256>>>(p_h1, p_agg1);
  }
  {
    long total = (long)NEDGES * (HID1 / 16);
    scatter_kernel<HID1><<<(unsigned)((total + 255) / 256), 256>>>(ei, p_h1, p_agg1);
  }
  {
    int total = NNODES * HID1;
    combine_drop_kernel<HID1><<<(total + 255) / 256, 256>>>(p_agg1, b1, p_h1, a0, a1);
  }

  // ---- layer 2: h2 = h1 @ W2 ; agg2 ; h2 = drop(tanh(agg2+b2))
  gemm_kernel<HID1, HID2, 8><<<(NNODES + 7) / 8, HID2 * 8>>>(
      p_h1, W2, nullptr, p_h2, NNODES);
  {
    long total4 = (long)NNODES * HID2 / 4;
    init_agg_kernel<HID2><<<(unsigned)((total4 + 255) / 256), 256>>>(p_h2, p_agg2);
  }
  {
    long total = (long)NEDGES * (HID2 / 16);
    scatter_kernel<HID2><<<(unsigned)((total + 255) / 256), 256>>>(ei, p_h2, p_agg2);
  }
  {
    int total = NNODES * HID2;
    combine_drop_kernel<HID2><<<(total + 255) / 256, 256>>>(p_agg2, b2, p_h2, c0, c1);
  }

  // ---- classifier: out = h2 @ Wl + bl
  gemm_kernel<HID2, NCLS, 25><<<(NNODES + 24) / 25, NCLS * 25>>>(
      p_h2, Wl, bl, out, NNODES);
}

// round 4
// speedup vs baseline: 1.9775x; 1.9775x over previous
#include <cuda_runtime.h>
#include <cstdint>

#define NNODES 50000
#define NEDGES 1600000
#define DFEAT  128
#define HID1   64
#define HID2   128
#define NCLS   40

// ---------------- scratch (static device globals; no runtime alloc) ----------
__device__ __align__(16) float g_h1raw[(size_t)NNODES * HID1];  // x @ W1
__device__ __align__(16) float g_h1   [(size_t)NNODES * HID1];  // post tanh+drop
__device__ __align__(16) float g_agg2 [(size_t)NNODES * HID1];  // A @ h1
__device__ __align__(16) float g_h2   [(size_t)NNODES * HID2];  // post layer2
__device__ int   g_deg   [NNODES];
__device__ float g_dinv  [NNODES];
__device__ float g_dinv2 [NNODES];
__device__ int   g_indptr[NNODES + 1];
__device__ int   g_cursor[NNODES];
__device__ __align__(8) int2 g_csc[NEDGES];   // (src, norm-as-int) grouped by dst

// ---------------- threefry2x32 (bit-exact JAX replica) -----------------------
__host__ __device__ __forceinline__ void threefry2x32(
    uint32_t k0, uint32_t k1, uint32_t x0, uint32_t x1,
    uint32_t& o0, uint32_t& o1) {
  uint32_t ks0 = k0, ks1 = k1, ks2 = k0 ^ k1 ^ 0x1BD11BDAu;
  x0 += ks0; x1 += ks1;
#define TF_ROT(v, d) (((v) << (d)) | ((v) >> (32 - (d))))
#define TF_RND(r) { x0 += x1; x1 = TF_ROT(x1, r); x1 ^= x0; }
  TF_RND(13) TF_RND(15) TF_RND(26) TF_RND(6)
  x0 += ks1; x1 += ks2 + 1u;
  TF_RND(17) TF_RND(29) TF_RND(16) TF_RND(24)
  x0 += ks2; x1 += ks0 + 2u;
  TF_RND(13) TF_RND(15) TF_RND(26) TF_RND(6)
  x0 += ks0; x1 += ks1 + 3u;
  TF_RND(17) TF_RND(29) TF_RND(16) TF_RND(24)
  x0 += ks1; x1 += ks2 + 4u;
  TF_RND(13) TF_RND(15) TF_RND(26) TF_RND(6)
  x0 += ks2; x1 += ks0 + 5u;
#undef TF_RND
#undef TF_ROT
  o0 = x0; o1 = x1;
}

// dropout(tanh(v + b)) for one element with flat index i
__device__ __forceinline__ float drop_tanh(float v, float b, uint32_t i,
                                           uint32_t k0, uint32_t k1) {
  uint32_t o0, o1;
  threefry2x32(k0, k1, 0u, i, o0, o1);
  uint32_t bits = o0 ^ o1;
  float u = __uint_as_float((bits >> 9) | 0x3f800000u) - 1.0f;
  float t = tanhf(v + b);
  return (u < 0.7f) ? (t * (1.0f / 0.7f)) : 0.0f;
}

// ---------------- degree / scan / csc build ----------------------------------
__global__ void zero_deg_kernel() {
  int i = blockIdx.x * blockDim.x + threadIdx.x;
  if (i < NNODES) g_deg[i] = 0;
}

__global__ void deg_count_kernel(const int* __restrict__ eidx) {
  int e = blockIdx.x * blockDim.x + threadIdx.x;
  if (e < NEDGES) {
    unsigned d = (unsigned)eidx[NEDGES + e];
    if (d < NNODES) atomicAdd(&g_deg[d], 1);
  }
}

__global__ void calc_dinv_kernel() {
  int i = blockIdx.x * blockDim.x + threadIdx.x;
  if (i < NNODES) {
    float d = (float)(g_deg[i] + 1);
    float di = rsqrtf(d);
    g_dinv[i]  = di;
    g_dinv2[i] = di * di;
  }
}

// single-block exclusive scan of g_deg -> g_indptr (+ copy to g_cursor)
__global__ void scan_kernel() {
  __shared__ int warp_sums[32];
  __shared__ int s_carry;
  const int tid = threadIdx.x, lane = tid & 31, wid = tid >> 5;
  if (tid == 0) s_carry = 0;
  __syncthreads();
  for (int base = 0; base < NNODES; base += 1024) {
    int i = base + tid;
    int v = (i < NNODES) ? g_deg[i] : 0;
    int x = v;
#pragma unroll
    for (int off = 1; off < 32; off <<= 1) {
      int t = __shfl_up_sync(0xffffffffu, x, off);
      if (lane >= off) x += t;
    }
    if (lane == 31) warp_sums[wid] = x;
    __syncthreads();
    if (wid == 0) {
      int w = warp_sums[lane];
#pragma unroll
      for (int off = 1; off < 32; off <<= 1) {
        int t = __shfl_up_sync(0xffffffffu, w, off);
        if (lane >= off) w += t;
      }
      warp_sums[lane] = w;
    }
    __syncthreads();
    int carry = s_carry;
    int woff = (wid == 0) ? 0 : warp_sums[wid - 1];
    if (i < NNODES) {
      int excl = carry + woff + x - v;
      g_indptr[i] = excl;
      g_cursor[i] = excl;
    }
    __syncthreads();
    if (tid == 1023) s_carry = carry + warp_sums[31];
    __syncthreads();
  }
  if (threadIdx.x == 0) g_indptr[NNODES] = s_carry;
}

__global__ void csc_fill_kernel(const int* __restrict__ eidx) {
  int e = blockIdx.x * blockDim.x + threadIdx.x;
  if (e < NEDGES) {
    unsigned s = (unsigned)eidx[e];
    unsigned d = (unsigned)eidx[NEDGES + e];
    if (s < NNODES && d < NNODES) {
      float n = g_dinv[s] * g_dinv[d];
      int pos = atomicAdd(&g_cursor[d], 1);
      g_csc[pos] = make_int2((int)s, __float_as_int(n));
    }
  }
}

// ---------------- GEMM: out[r,c] = A[r,:K] @ W[:K,c] (+bias, opt tanh+drop) --
template <int K, int NC, int RPB, int EPI>
__global__ void gemm_kernel(const float* __restrict__ A,
                            const float* __restrict__ W,
                            const float* __restrict__ bias,
                            float* __restrict__ out,
                            uint32_t k0, uint32_t k1) {
  __shared__ float Ws[K * NC];
  __shared__ float As[RPB * K];
  constexpr int NT = RPB * NC / 4;
  const int tid = threadIdx.x;
  for (int i = tid; i < K * NC / 4; i += NT)
    ((float4*)Ws)[i] = ((const float4*)W)[i];
  const int row0 = blockIdx.x * RPB;
  for (int i = tid; i < RPB * K / 4; i += NT) {
    int r = i / (K / 4);
    int gr = row0 + r;
    ((float4*)As)[i] = (gr < NNODES)
        ? ((const float4*)A)[(long)gr * (K / 4) + (i % (K / 4))]
        : make_float4(0.f, 0.f, 0.f, 0.f);
  }
  __syncthreads();
  const int c4 = (tid % (NC / 4)) * 4;
  const int r  = tid / (NC / 4);
  float4 acc;
  if (bias) { acc.x = bias[c4]; acc.y = bias[c4 + 1];
              acc.z = bias[c4 + 2]; acc.w = bias[c4 + 3]; }
  else      { acc = make_float4(0.f, 0.f, 0.f, 0.f); }
  const float* as = &As[r * K];
#pragma unroll 8
  for (int k = 0; k < K; k++) {
    float a = as[k];
    float4 w = *(const float4*)&Ws[k * NC + c4];
    acc.x = fmaf(a, w.x, acc.x);
    acc.y = fmaf(a, w.y, acc.y);
    acc.z = fmaf(a, w.z, acc.z);
    acc.w = fmaf(a, w.w, acc.w);
  }
  int gr = row0 + r;
  if (gr < NNODES) {
    if (EPI) {
      uint32_t i0 = (uint32_t)gr * NC + c4;
      acc.x = drop_tanh(acc.x, 0.f, i0,     k0, k1);
      acc.y = drop_tanh(acc.y, 0.f, i0 + 1, k0, k1);
      acc.z = drop_tanh(acc.z, 0.f, i0 + 2, k0, k1);
      acc.w = drop_tanh(acc.w, 0.f, i0 + 3, k0, k1);
    }
    *(float4*)&out[(long)gr * NC + c4] = acc;
  }
}

// ---------------- pull aggregation (H=64, one warp per dst node) -------------
// out[dst] = sum_in_edges h[src]*norm + h[dst]*dinv2[dst]  (+ optional epilogue)
template <int EPI>
__global__ void gather64_kernel(const float* __restrict__ h,
                                const float* __restrict__ bias,
                                float* __restrict__ out,
                                uint32_t k0, uint32_t k1) {
  const int node = blockIdx.x * (blockDim.x >> 5) + (threadIdx.x >> 5);
  if (node >= NNODES) return;
  const int lane = threadIdx.x & 31;
  const int beg = g_indptr[node];
  const int end = g_indptr[node + 1];
  float2 acc = make_float2(0.f, 0.f);
  int e = beg;
  for (; e + 3 < end; e += 4) {
    int2 m0 = g_csc[e],     m1 = g_csc[e + 1];
    int2 m2 = g_csc[e + 2], m3 = g_csc[e + 3];
    float2 v0 = *(const float2*)(h + (long)m0.x * HID1 + lane * 2);
    float2 v1 = *(const float2*)(h + (long)m1.x * HID1 + lane * 2);
    float2 v2 = *(const float2*)(h + (long)m2.x * HID1 + lane * 2);
    float2 v3 = *(const float2*)(h + (long)m3.x * HID1 + lane * 2);
    float n0 = __int_as_float(m0.y), n1 = __int_as_float(m1.y);
    float n2 = __int_as_float(m2.y), n3 = __int_as_float(m3.y);
    acc.x = fmaf(v0.x, n0, acc.x); acc.y = fmaf(v0.y, n0, acc.y);
    acc.x = fmaf(v1.x, n1, acc.x); acc.y = fmaf(v1.y, n1, acc.y);
    acc.x = fmaf(v2.x, n2, acc.x); acc.y = fmaf(v2.y, n2, acc.y);
    acc.x = fmaf(v3.x, n3, acc.x); acc.y = fmaf(v3.y, n3, acc.y);
  }
  for (; e < end; e++) {
    int2 m = g_csc[e];
    float2 v = *(const float2*)(h + (long)m.x * HID1 + lane * 2);
    float n = __int_as_float(m.y);
    acc.x = fmaf(v.x, n, acc.x); acc.y = fmaf(v.y, n, acc.y);
  }
  // self-loop term
  float2 vs = *(const float2*)(h + (long)node * HID1 + lane * 2);
  float d2 = g_dinv2[node];
  acc.x = fmaf(vs.x, d2, acc.x);
  acc.y = fmaf(vs.y, d2, acc.y);

  const int c = lane * 2;
  if (EPI) {
    uint32_t i0 = (uint32_t)node * HID1 + c;
    acc.x = drop_tanh(acc.x, bias[c],     i0,     k0, k1);
    acc.y = drop_tanh(acc.y, bias[c + 1], i0 + 1, k0, k1);
  }
  *(float2*)(out + (long)node * HID1 + c) = acc;
}

// ---------------- launch ------------------------------------------------------
extern "C" void kernel_launch(void* const* d_in, const int* in_sizes, int n_in,
                              void* d_out, int out_size) {
  const float* x  = (const float*)d_in[0];
  const int*   ei = (const int*)d_in[1];  // int32 [2, E]
  const float* W1 = (const float*)d_in[2];
  const float* b1 = (const float*)d_in[3];
  const float* W2 = (const float*)d_in[4];
  const float* b2 = (const float*)d_in[5];
  const float* Wl = (const float*)d_in[6];
  const float* bl = (const float*)d_in[7];
  float* out = (float*)d_out;

  // JAX split(key(42)), threefry_partitionable (foldlike):
  uint32_t a0, a1, c0, c1;
  threefry2x32(0u, 42u, 0u, 0u, a0, a1);  // dk1
  threefry2x32(0u, 42u, 0u, 1u, c0, c1);  // dk2

  float *p_h1raw, *p_h1, *p_agg2, *p_h2;
  cudaGetSymbolAddress((void**)&p_h1raw, g_h1raw);
  cudaGetSymbolAddress((void**)&p_h1,    g_h1);
  cudaGetSymbolAddress((void**)&p_agg2,  g_agg2);
  cudaGetSymbolAddress((void**)&p_h2,    g_h2);

  // ---- CSC build
  zero_deg_kernel <<<(NNODES + 255) / 256, 256>>>();
  deg_count_kernel<<<(NEDGES + 255) / 256, 256>>>(ei);
  calc_dinv_kernel<<<(NNODES + 255) / 256, 256>>>();
  scan_kernel     <<<1, 1024>>>();
  csc_fill_kernel <<<(NEDGES + 255) / 256, 256>>>(ei);

  // ---- layer 1: h1raw = x @ W1 ; h1 = drop(tanh(A@h1raw + b1))
  gemm_kernel<DFEAT, HID1, 16, 0><<<(NNODES + 15) / 16, 16 * HID1 / 4>>>(
      x, W1, nullptr, p_h1raw, 0u, 0u);
  gather64_kernel<1><<<(NNODES + 7) / 8, 256>>>(p_h1raw, b1, p_h1, a0, a1);

  // ---- layer 2: agg2 = A@h1 (width 64) ; h2 = drop(tanh(agg2 @ W2 + b2))
  gather64_kernel<0><<<(NNODES + 7) / 8, 256>>>(p_h1, nullptr, p_agg2, 0u, 0u);
  gemm_kernel<HID1, HID2, 8, 1><<<(NNODES + 7) / 8, 8 * HID2 / 4>>>(
      p_agg2, W2, b2, p_h2, c0, c1);

  // ---- classifier: out = h2 @ Wl + bl
  gemm_kernel<HID2, NCLS, 25, 0><<<(NNODES + 24) / 25, 25 * NCLS / 4>>>(
      p_h2, Wl, bl, out, 0u, 0u);
}

// round 5
// speedup vs baseline: 2.7428x; 1.3870x over previous
#include <cuda_runtime.h>
#include <cstdint>

#define NNODES 50000
#define NEDGES 1600000
#define DFEAT  128
#define HID1   64
#define HID2   128
#define NCLS   40
#define NBLK   196   // ceil(NNODES / 256)

// ---------------- scratch (static device globals; no runtime alloc) ----------
__device__ __align__(16) float g_hp1 [(size_t)NNODES * HID1];  // (x@W1)*dinv
__device__ __align__(16) float g_h1p [(size_t)NNODES * HID1];  // layer1 out, prescaled
__device__ __align__(16) float g_agg2[(size_t)NNODES * HID1];  // A @ h1
__device__ __align__(16) float g_h2  [(size_t)NNODES * HID2];  // layer2 out
__device__ int   g_deg   [NNODES];
__device__ float g_dinv  [NNODES];
__device__ int   g_indptr[NNODES + 1];
__device__ int   g_cursor[NNODES];
__device__ int   g_csc_src[NEDGES];
__device__ int   g_bsum[NBLK];
__device__ int   g_boff[NBLK];

// ---------------- threefry2x32 (bit-exact JAX replica) -----------------------
__host__ __device__ __forceinline__ void threefry2x32(
    uint32_t k0, uint32_t k1, uint32_t x0, uint32_t x1,
    uint32_t& o0, uint32_t& o1) {
  uint32_t ks0 = k0, ks1 = k1, ks2 = k0 ^ k1 ^ 0x1BD11BDAu;
  x0 += ks0; x1 += ks1;
#define TF_ROT(v, d) (((v) << (d)) | ((v) >> (32 - (d))))
#define TF_RND(r) { x0 += x1; x1 = TF_ROT(x1, r); x1 ^= x0; }
  TF_RND(13) TF_RND(15) TF_RND(26) TF_RND(6)
  x0 += ks1; x1 += ks2 + 1u;
  TF_RND(17) TF_RND(29) TF_RND(16) TF_RND(24)
  x0 += ks2; x1 += ks0 + 2u;
  TF_RND(13) TF_RND(15) TF_RND(26) TF_RND(6)
  x0 += ks0; x1 += ks1 + 3u;
  TF_RND(17) TF_RND(29) TF_RND(16) TF_RND(24)
  x0 += ks1; x1 += ks2 + 4u;
  TF_RND(13) TF_RND(15) TF_RND(26) TF_RND(6)
  x0 += ks2; x1 += ks0 + 5u;
#undef TF_RND
#undef TF_ROT
  o0 = x0; o1 = x1;
}

__device__ __forceinline__ float drop_tanh(float v, float b, uint32_t i,
                                           uint32_t k0, uint32_t k1) {
  uint32_t o0, o1;
  threefry2x32(k0, k1, 0u, i, o0, o1);
  uint32_t bits = o0 ^ o1;
  float u = __uint_as_float((bits >> 9) | 0x3f800000u) - 1.0f;
  float t = tanhf(v + b);
  return (u < 0.7f) ? (t * (1.0f / 0.7f)) : 0.0f;
}

// ---------------- degree + parallel scan + csc build -------------------------
__global__ void zero_deg_kernel() {
  int i = blockIdx.x * blockDim.x + threadIdx.x;
  if (i < NNODES) g_deg[i] = 0;
}

__global__ void deg_count_kernel(const int* __restrict__ eidx) {
  int e = blockIdx.x * blockDim.x + threadIdx.x;
  if (e < NEDGES) {
    unsigned d = (unsigned)eidx[NEDGES + e];
    if (d < NNODES) atomicAdd(&g_deg[d], 1);
  }
}

__global__ void reduce_deg_kernel() {   // grid NBLK, block 256
  __shared__ int sdata[256];
  int i = blockIdx.x * 256 + threadIdx.x;
  sdata[threadIdx.x] = (i < NNODES) ? g_deg[i] : 0;
  __syncthreads();
  for (int s = 128; s > 0; s >>= 1) {
    if (threadIdx.x < s) sdata[threadIdx.x] += sdata[threadIdx.x + s];
    __syncthreads();
  }
  if (threadIdx.x == 0) g_bsum[blockIdx.x] = sdata[0];
}

__global__ void scan_bsum_kernel() {    // 1 block, 256 threads
  const int tid = threadIdx.x, lane = tid & 31, w = tid >> 5;
  __shared__ int ws[9];
  int v = (tid < NBLK) ? g_bsum[tid] : 0;
  int x = v;
#pragma unroll
  for (int o = 1; o < 32; o <<= 1) {
    int t = __shfl_up_sync(0xffffffffu, x, o);
    if (lane >= o) x += t;
  }
  if (lane == 31) ws[w] = x;
  __syncthreads();
  if (tid == 0) {
    int run = 0;
    for (int j = 0; j < 8; j++) { int t = ws[j]; ws[j] = run; run += t; }
    ws[8] = run;
  }
  __syncthreads();
  if (tid < NBLK) g_boff[tid] = x - v + ws[w];
  if (tid == 0) g_indptr[NNODES] = ws[8];
}

__global__ void finalize_kernel() {     // grid NBLK, block 256: indptr+cursor+dinv
  const int tid = threadIdx.x, lane = tid & 31, w = tid >> 5;
  __shared__ int ws[8];
  int i = blockIdx.x * 256 + tid;
  int v = (i < NNODES) ? g_deg[i] : 0;
  int x = v;
#pragma unroll
  for (int o = 1; o < 32; o <<= 1) {
    int t = __shfl_up_sync(0xffffffffu, x, o);
    if (lane >= o) x += t;
  }
  if (lane == 31) ws[w] = x;
  __syncthreads();
  if (tid == 0) {
    int run = 0;
    for (int j = 0; j < 8; j++) { int t = ws[j]; ws[j] = run; run += t; }
  }
  __syncthreads();
  if (i < NNODES) {
    int excl = g_boff[blockIdx.x] + ws[w] + x - v;
    g_indptr[i] = excl;
    g_cursor[i] = excl;
    g_dinv[i] = rsqrtf((float)(v + 1));
  }
}

__global__ void csc_fill_kernel(const int* __restrict__ eidx) {
  int e = blockIdx.x * blockDim.x + threadIdx.x;
  if (e < NEDGES) {
    unsigned s = (unsigned)eidx[e];
    unsigned d = (unsigned)eidx[NEDGES + e];
    if (s < NNODES && d < NNODES) {
      int pos = atomicAdd(&g_cursor[d], 1);
      g_csc_src[pos] = (int)s;
    }
  }
}

// ---------------- register-tiled GEMM (BM=64, KT=64, 4x4 per thread) ---------
// MODE 0: plain (+bias)   MODE 1: bias + tanh + dropout   MODE 2: *dinv[row]
template <int K, int NC, int MODE>
__global__ __launch_bounds__(16 * (NC / 4))
void gemm_tiled(const float* __restrict__ A, const float* __restrict__ W,
                const float* __restrict__ bias, float* __restrict__ out,
                uint32_t k0, uint32_t k1) {
  constexpr int NT = 16 * (NC / 4);
  __shared__ float As[64 * 64];
  __shared__ float Ws[64 * NC];
  const int tid = threadIdx.x;
  const int row0 = blockIdx.x * 64;
  const int mg = tid / (NC / 4);
  const int ng = tid % (NC / 4);
  const int m0 = mg * 4, c4 = ng * 4;
  float4 bv = make_float4(0.f, 0.f, 0.f, 0.f);
  if (MODE == 1) bv = *(const float4*)&bias[c4];
  float4 acc[4] = {bv, bv, bv, bv};

  for (int kt = 0; kt < K; kt += 64) {
#pragma unroll 2
    for (int t = tid; t < 64 * 16; t += NT) {
      int r = t / 16, kk4 = (t % 16) * 4;
      int gr = row0 + r;
      float4 val = (gr < NNODES) ? *(const float4*)&A[(long)gr * K + kt + kk4]
                                 : make_float4(0.f, 0.f, 0.f, 0.f);
      *(float4*)&As[r * 64 + kk4] = val;
    }
    for (int t = tid; t < 64 * (NC / 4); t += NT) {
      int kk = t / (NC / 4), cc4 = (t % (NC / 4)) * 4;
      *(float4*)&Ws[kk * NC + cc4] = *(const float4*)&W[(long)(kt + kk) * NC + cc4];
    }
    __syncthreads();
#pragma unroll 8
    for (int kk = 0; kk < 64; kk++) {
      float a0 = As[(m0 + 0) * 64 + kk];
      float a1 = As[(m0 + 1) * 64 + kk];
      float a2 = As[(m0 + 2) * 64 + kk];
      float a3 = As[(m0 + 3) * 64 + kk];
      float4 wv = *(const float4*)&Ws[kk * NC + c4];
      acc[0].x = fmaf(a0, wv.x, acc[0].x); acc[0].y = fmaf(a0, wv.y, acc[0].y);
      acc[0].z = fmaf(a0, wv.z, acc[0].z); acc[0].w = fmaf(a0, wv.w, acc[0].w);
      acc[1].x = fmaf(a1, wv.x, acc[1].x); acc[1].y = fmaf(a1, wv.y, acc[1].y);
      acc[1].z = fmaf(a1, wv.z, acc[1].z); acc[1].w = fmaf(a1, wv.w, acc[1].w);
      acc[2].x = fmaf(a2, wv.x, acc[2].x); acc[2].y = fmaf(a2, wv.y, acc[2].y);
      acc[2].z = fmaf(a2, wv.z, acc[2].z); acc[2].w = fmaf(a2, wv.w, acc[2].w);
      acc[3].x = fmaf(a3, wv.x, acc[3].x); acc[3].y = fmaf(a3, wv.y, acc[3].y);
      acc[3].z = fmaf(a3, wv.z, acc[3].z); acc[3].w = fmaf(a3, wv.w, acc[3].w);
    }
    __syncthreads();
  }
#pragma unroll
  for (int i = 0; i < 4; i++) {
    int gr = row0 + m0 + i;
    if (gr >= NNODES) continue;
    float4 r = acc[i];
    if (MODE == 2) {
      float di = g_dinv[gr];
      r.x *= di; r.y *= di; r.z *= di; r.w *= di;
    }
    if (MODE == 1) {
      uint32_t i0 = (uint32_t)gr * NC + c4;
      r.x = drop_tanh(r.x, 0.f, i0,     k0, k1);
      r.y = drop_tanh(r.y, 0.f, i0 + 1, k0, k1);
      r.z = drop_tanh(r.z, 0.f, i0 + 2, k0, k1);
      r.w = drop_tanh(r.w, 0.f, i0 + 3, k0, k1);
    }
    *(float4*)&out[(long)gr * NC + c4] = r;
  }
}

// ---------------- small GEMM for classifier (NC=40) --------------------------
template <int K, int NC, int RPB>
__global__ void gemm_small(const float* __restrict__ A,
                           const float* __restrict__ W,
                           const float* __restrict__ bias,
                           float* __restrict__ out) {
  __shared__ float Ws[K * NC];
  __shared__ float As[RPB * K];
  constexpr int NT = RPB * NC / 4;
  const int tid = threadIdx.x;
  for (int i = tid; i < K * NC / 4; i += NT)
    ((float4*)Ws)[i] = ((const float4*)W)[i];
  const int row0 = blockIdx.x * RPB;
  for (int i = tid; i < RPB * K / 4; i += NT) {
    int r = i / (K / 4);
    int gr = row0 + r;
    ((float4*)As)[i] = (gr < NNODES)
        ? ((const float4*)A)[(long)gr * (K / 4) + (i % (K / 4))]
        : make_float4(0.f, 0.f, 0.f, 0.f);
  }
  __syncthreads();
  const int c4 = (tid % (NC / 4)) * 4;
  const int r  = tid / (NC / 4);
  float4 acc = *(const float4*)&bias[c4];
  const float* as = &As[r * K];
#pragma unroll 8
  for (int k = 0; k < K; k++) {
    float a = as[k];
    float4 w = *(const float4*)&Ws[k * NC + c4];
    acc.x = fmaf(a, w.x, acc.x);
    acc.y = fmaf(a, w.y, acc.y);
    acc.z = fmaf(a, w.z, acc.z);
    acc.w = fmaf(a, w.w, acc.w);
  }
  int gr = row0 + r;
  if (gr < NNODES) *(float4*)&out[(long)gr * NC + c4] = acc;
}

// ---------------- pull aggregation (H=64, warp per node, norm-free) ----------
// out = f( dinv[d] * (sum_{e in(d)} h'[src] + h'[d]) )
// MODE 1: f = drop_tanh(.+bias)*dinv[d]   MODE 0: f = identity
template <int MODE>
__global__ void gather64_kernel(const float* __restrict__ h,
                                const float* __restrict__ bias,
                                float* __restrict__ out,
                                uint32_t k0, uint32_t k1) {
  const int node = blockIdx.x * (blockDim.x >> 5) + (threadIdx.x >> 5);
  if (node >= NNODES) return;
  const int lane = threadIdx.x & 31;
  const int beg = g_indptr[node];
  const int end = g_indptr[node + 1];
  float2 a0 = make_float2(0.f, 0.f), a1 = make_float2(0.f, 0.f);
  int e = beg;
  for (; e + 3 < end; e += 4) {
    int s0 = g_csc_src[e],     s1 = g_csc_src[e + 1];
    int s2 = g_csc_src[e + 2], s3 = g_csc_src[e + 3];
    float2 v0 = *(const float2*)(h + (long)s0 * HID1 + lane * 2);
    float2 v1 = *(const float2*)(h + (long)s1 * HID1 + lane * 2);
    float2 v2 = *(const float2*)(h + (long)s2 * HID1 + lane * 2);
    float2 v3 = *(const float2*)(h + (long)s3 * HID1 + lane * 2);
    a0.x += v0.x; a0.y += v0.y; a1.x += v1.x; a1.y += v1.y;
    a0.x += v2.x; a0.y += v2.y; a1.x += v3.x; a1.y += v3.y;
  }
  for (; e < end; e++) {
    int s = g_csc_src[e];
    float2 v = *(const float2*)(h + (long)s * HID1 + lane * 2);
    a0.x += v.x; a0.y += v.y;
  }
  float2 vs = *(const float2*)(h + (long)node * HID1 + lane * 2);
  float sx = a0.x + a1.x + vs.x;
  float sy = a0.y + a1.y + vs.y;
  float di = g_dinv[node];
  float vx = sx * di, vy = sy * di;
  const int c = lane * 2;
  if (MODE == 1) {
    uint32_t i0 = (uint32_t)node * HID1 + c;
    vx = drop_tanh(vx, bias[c],     i0,     k0, k1) * di;
    vy = drop_tanh(vy, bias[c + 1], i0 + 1, k0, k1) * di;
  }
  *(float2*)(out + (long)node * HID1 + c) = make_float2(vx, vy);
}

// ---------------- launch ------------------------------------------------------
extern "C" void kernel_launch(void* const* d_in, const int* in_sizes, int n_in,
                              void* d_out, int out_size) {
  const float* x  = (const float*)d_in[0];
  const int*   ei = (const int*)d_in[1];
  const float* W1 = (const float*)d_in[2];
  const float* b1 = (const float*)d_in[3];
  const float* W2 = (const float*)d_in[4];
  const float* b2 = (const float*)d_in[5];
  const float* Wl = (const float*)d_in[6];
  const float* bl = (const float*)d_in[7];
  float* out = (float*)d_out;

  uint32_t a0, a1, c0, c1;
  threefry2x32(0u, 42u, 0u, 0u, a0, a1);  // dk1
  threefry2x32(0u, 42u, 0u, 1u, c0, c1);  // dk2

  float *p_hp1, *p_h1p, *p_agg2, *p_h2;
  cudaGetSymbolAddress((void**)&p_hp1,  g_hp1);
  cudaGetSymbolAddress((void**)&p_h1p,  g_h1p);
  cudaGetSymbolAddress((void**)&p_agg2, g_agg2);
  cudaGetSymbolAddress((void**)&p_h2,   g_h2);

  // ---- CSC build (parallel scan + dinv fused into finalize)
  zero_deg_kernel  <<<(NNODES + 255) / 256, 256>>>();
  deg_count_kernel <<<(NEDGES + 255) / 256, 256>>>(ei);
  reduce_deg_kernel<<<NBLK, 256>>>();
  scan_bsum_kernel <<<1, 256>>>();
  finalize_kernel  <<<NBLK, 256>>>();
  csc_fill_kernel  <<<(NEDGES + 255) / 256, 256>>>(ei);

  // ---- layer 1: hp1 = (x@W1)*dinv ; h1p = drop(tanh(dinv*(sum+self)+b1))*dinv
  gemm_tiled<DFEAT, HID1, 2><<<(NNODES + 63) / 64, 256>>>(
      x, W1, nullptr, p_hp1, 0u, 0u);
  gather64_kernel<1><<<(NNODES + 7) / 8, 256>>>(p_hp1, b1, p_h1p, a0, a1);

  // ---- layer 2: agg2 = dinv*(sum+self) ; h2 = drop(tanh(agg2@W2 + b2))
  gather64_kernel<0><<<(NNODES + 7) / 8, 256>>>(p_h1p, nullptr, p_agg2, 0u, 0u);
  gemm_tiled<HID1, HID2, 1><<<(NNODES + 63) / 64, 512>>>(
      p_agg2, W2, b2, p_h2, c0, c1);

  // ---- classifier
  gemm_small<HID2, NCLS, 25><<<(NNODES + 24) / 25, 250>>>(p_h2, Wl, bl, out);
}

// round 6
// speedup vs baseline: 3.1134x; 1.1351x over previous
#include <cuda_runtime.h>
#include <cuda_fp16.h>
#include <cstdint>

#define NNODES 50000
#define NEDGES 1600000
#define DFEAT  128
#define HID1   64
#define HID2   128
#define NCLS   40
#define NBLK   196   // ceil(NNODES / 256)

// ---------------- scratch (static device globals; no runtime alloc) ----------
__device__ __align__(16) __half2 g_hp1h[(size_t)NNODES * (HID1 / 2)]; // (x@W1)*dinv
__device__ __align__(16) __half2 g_h1ph[(size_t)NNODES * (HID1 / 2)]; // layer1 out, prescaled
__device__ __align__(16) float   g_agg2[(size_t)NNODES * HID1];       // A @ h1
__device__ __align__(16) float   g_h2  [(size_t)NNODES * HID2];       // layer2 out
__device__ int   g_deg   [NNODES];
__device__ float g_dinv  [NNODES];
__device__ int   g_indptr[NNODES + 1];
__device__ int   g_cursor[NNODES];
__device__ int   g_csc_src[NEDGES];
__device__ int   g_bsum[NBLK];
__device__ int   g_boff[NBLK];

// ---------------- threefry2x32 (bit-exact JAX replica) -----------------------
__host__ __device__ __forceinline__ void threefry2x32(
    uint32_t k0, uint32_t k1, uint32_t x0, uint32_t x1,
    uint32_t& o0, uint32_t& o1) {
  uint32_t ks0 = k0, ks1 = k1, ks2 = k0 ^ k1 ^ 0x1BD11BDAu;
  x0 += ks0; x1 += ks1;
#define TF_ROT(v, d) (((v) << (d)) | ((v) >> (32 - (d))))
#define TF_RND(r) { x0 += x1; x1 = TF_ROT(x1, r); x1 ^= x0; }
  TF_RND(13) TF_RND(15) TF_RND(26) TF_RND(6)
  x0 += ks1; x1 += ks2 + 1u;
  TF_RND(17) TF_RND(29) TF_RND(16) TF_RND(24)
  x0 += ks2; x1 += ks0 + 2u;
  TF_RND(13) TF_RND(15) TF_RND(26) TF_RND(6)
  x0 += ks0; x1 += ks1 + 3u;
  TF_RND(17) TF_RND(29) TF_RND(16) TF_RND(24)
  x0 += ks1; x1 += ks2 + 4u;
  TF_RND(13) TF_RND(15) TF_RND(26) TF_RND(6)
  x0 += ks2; x1 += ks0 + 5u;
#undef TF_RND
#undef TF_ROT
  o0 = x0; o1 = x1;
}

__device__ __forceinline__ float drop_tanh(float v, float b, uint32_t i,
                                           uint32_t k0, uint32_t k1) {
  uint32_t o0, o1;
  threefry2x32(k0, k1, 0u, i, o0, o1);
  uint32_t bits = o0 ^ o1;
  float u = __uint_as_float((bits >> 9) | 0x3f800000u) - 1.0f;
  float t = tanhf(v + b);
  return (u < 0.7f) ? (t * (1.0f / 0.7f)) : 0.0f;
}

// ---------------- degree + parallel scan + csc build -------------------------
__global__ void zero_deg_kernel() {
  int i = blockIdx.x * blockDim.x + threadIdx.x;
  if (i < NNODES) g_deg[i] = 0;
}

__global__ void deg_count_kernel(const int* __restrict__ eidx) {   // 2 edges/thr
  int e2 = blockIdx.x * blockDim.x + threadIdx.x;
  int e = e2 * 2;
  if (e < NEDGES) {
    int2 d = *(const int2*)&eidx[NEDGES + e];
    if ((unsigned)d.x < NNODES) atomicAdd(&g_deg[d.x], 1);
    if ((unsigned)d.y < NNODES) atomicAdd(&g_deg[d.y], 1);
  }
}

__global__ void reduce_deg_kernel() {   // grid NBLK, block 256
  __shared__ int sdata[256];
  int i = blockIdx.x * 256 + threadIdx.x;
  sdata[threadIdx.x] = (i < NNODES) ? g_deg[i] : 0;
  __syncthreads();
  for (int s = 128; s > 0; s >>= 1) {
    if (threadIdx.x < s) sdata[threadIdx.x] += sdata[threadIdx.x + s];
    __syncthreads();
  }
  if (threadIdx.x == 0) g_bsum[blockIdx.x] = sdata[0];
}

__global__ void scan_bsum_kernel() {    // 1 block, 256 threads
  const int tid = threadIdx.x, lane = tid & 31, w = tid >> 5;
  __shared__ int ws[9];
  int v = (tid < NBLK) ? g_bsum[tid] : 0;
  int x = v;
#pragma unroll
  for (int o = 1; o < 32; o <<= 1) {
    int t = __shfl_up_sync(0xffffffffu, x, o);
    if (lane >= o) x += t;
  }
  if (lane == 31) ws[w] = x;
  __syncthreads();
  if (tid == 0) {
    int run = 0;
    for (int j = 0; j < 8; j++) { int t = ws[j]; ws[j] = run; run += t; }
    ws[8] = run;
  }
  __syncthreads();
  if (tid < NBLK) g_boff[tid] = x - v + ws[w];
  if (tid == 0) g_indptr[NNODES] = ws[8];
}

__global__ void finalize_kernel() {     // grid NBLK: indptr+cursor+dinv
  const int tid = threadIdx.x, lane = tid & 31, w = tid >> 5;
  __shared__ int ws[8];
  int i = blockIdx.x * 256 + tid;
  int v = (i < NNODES) ? g_deg[i] : 0;
  int x = v;
#pragma unroll
  for (int o = 1; o < 32; o <<= 1) {
    int t = __shfl_up_sync(0xffffffffu, x, o);
    if (lane >= o) x += t;
  }
  if (lane == 31) ws[w] = x;
  __syncthreads();
  if (tid == 0) {
    int run = 0;
    for (int j = 0; j < 8; j++) { int t = ws[j]; ws[j] = run; run += t; }
  }
  __syncthreads();
  if (i < NNODES) {
    int excl = g_boff[blockIdx.x] + ws[w] + x - v;
    g_indptr[i] = excl;
    g_cursor[i] = excl;
    g_dinv[i] = rsqrtf((float)(v + 1));
  }
}

__global__ void csc_fill_kernel(const int* __restrict__ eidx) {   // 2 edges/thr
  int e2 = blockIdx.x * blockDim.x + threadIdx.x;
  int e = e2 * 2;
  if (e < NEDGES) {
    int2 s = *(const int2*)&eidx[e];
    int2 d = *(const int2*)&eidx[NEDGES + e];
    if ((unsigned)s.x < NNODES && (unsigned)d.x < NNODES) {
      int pos = atomicAdd(&g_cursor[d.x], 1);
      g_csc_src[pos] = s.x;
    }
    if ((unsigned)s.y < NNODES && (unsigned)d.y < NNODES) {
      int pos = atomicAdd(&g_cursor[d.y], 1);
      g_csc_src[pos] = s.y;
    }
  }
}

// ---------------- register-tiled GEMM (BM=64, 4x4 per thread) ----------------
// MODE 0: +bias (if non-null), float out
// MODE 1: +bias, tanh+dropout, float out
// MODE 2: *dinv[row], half2 out
template <int K, int NC, int MODE>
__global__ __launch_bounds__(16 * (NC / 4))
void gemm_tiled(const float* __restrict__ A, const float* __restrict__ W,
                const float* __restrict__ bias, void* __restrict__ out_,
                uint32_t k0, uint32_t k1) {
  constexpr int NT = 16 * (NC / 4);
  __shared__ float As[64 * 64];
  __shared__ float Ws[64 * NC];
  const int tid = threadIdx.x;
  const int row0 = blockIdx.x * 64;
  const int mg = tid / (NC / 4);
  const int ng = tid % (NC / 4);
  const int m0 = mg * 4, c4 = ng * 4;
  float4 bv = make_float4(0.f, 0.f, 0.f, 0.f);
  if ((MODE == 0 || MODE == 1) && bias) bv = *(const float4*)&bias[c4];
  float4 acc[4] = {bv, bv, bv, bv};

  for (int kt = 0; kt < K; kt += 64) {
#pragma unroll 2
    for (int t = tid; t < 64 * 16; t += NT) {
      int r = t / 16, kk4 = (t % 16) * 4;
      int gr = row0 + r;
      float4 val = (gr < NNODES) ? *(const float4*)&A[(long)gr * K + kt + kk4]
                                 : make_float4(0.f, 0.f, 0.f, 0.f);
      *(float4*)&As[r * 64 + kk4] = val;
    }
    for (int t = tid; t < 64 * (NC / 4); t += NT) {
      int kk = t / (NC / 4), cc4 = (t % (NC / 4)) * 4;
      *(float4*)&Ws[kk * NC + cc4] = *(const float4*)&W[(long)(kt + kk) * NC + cc4];
    }
    __syncthreads();
#pragma unroll 8
    for (int kk = 0; kk < 64; kk++) {
      float a0 = As[(m0 + 0) * 64 + kk];
      float a1 = As[(m0 + 1) * 64 + kk];
      float a2 = As[(m0 + 2) * 64 + kk];
      float a3 = As[(m0 + 3) * 64 + kk];
      float4 wv = *(const float4*)&Ws[kk * NC + c4];
      acc[0].x = fmaf(a0, wv.x, acc[0].x); acc[0].y = fmaf(a0, wv.y, acc[0].y);
      acc[0].z = fmaf(a0, wv.z, acc[0].z); acc[0].w = fmaf(a0, wv.w, acc[0].w);
      acc[1].x = fmaf(a1, wv.x, acc[1].x); acc[1].y = fmaf(a1, wv.y, acc[1].y);
      acc[1].z = fmaf(a1, wv.z, acc[1].z); acc[1].w = fmaf(a1, wv.w, acc[1].w);
      acc[2].x = fmaf(a2, wv.x, acc[2].x); acc[2].y = fmaf(a2, wv.y, acc[2].y);
      acc[2].z = fmaf(a2, wv.z, acc[2].z); acc[2].w = fmaf(a2, wv.w, acc[2].w);
      acc[3].x = fmaf(a3, wv.x, acc[3].x); acc[3].y = fmaf(a3, wv.y, acc[3].y);
      acc[3].z = fmaf(a3, wv.z, acc[3].z); acc[3].w = fmaf(a3, wv.w, acc[3].w);
    }
    __syncthreads();
  }
#pragma unroll
  for (int i = 0; i < 4; i++) {
    int gr = row0 + m0 + i;
    if (gr >= NNODES) continue;
    float4 r = acc[i];
    if (MODE == 2) {
      float di = g_dinv[gr];
      r.x *= di; r.y *= di; r.z *= di; r.w *= di;
      __half2 p0 = __floats2half2_rn(r.x, r.y);
      __half2 p1 = __floats2half2_rn(r.z, r.w);
      __half2* oh = (__half2*)out_;
      uint32_t u0 = *reinterpret_cast<uint32_t*>(&p0);
      uint32_t u1 = *reinterpret_cast<uint32_t*>(&p1);
      *reinterpret_cast<uint2*>(&oh[(size_t)gr * (NC / 2) + (c4 >> 1)]) =
          make_uint2(u0, u1);
    } else {
      if (MODE == 1) {
        uint32_t i0 = (uint32_t)gr * NC + c4;
        r.x = drop_tanh(r.x, 0.f, i0,     k0, k1);
        r.y = drop_tanh(r.y, 0.f, i0 + 1, k0, k1);
        r.z = drop_tanh(r.z, 0.f, i0 + 2, k0, k1);
        r.w = drop_tanh(r.w, 0.f, i0 + 3, k0, k1);
      }
      *(float4*)&((float*)out_)[(long)gr * NC + c4] = r;
    }
  }
}

// ---------------- pull aggregation (H=64 fp16 in, warp per node) -------------
// sum = dinv[d] * (sum_in h'[src] + h'[d])
// MODE 1: out_h[.] = half( drop_tanh(sum + bias) * dinv[d] )
// MODE 0: out_f[.] = sum
template <int MODE>
__global__ void gather64_kernel(const __half2* __restrict__ h,
                                const float* __restrict__ bias,
                                void* __restrict__ out_,
                                uint32_t k0, uint32_t k1) {
  const int node = blockIdx.x * (blockDim.x >> 5) + (threadIdx.x >> 5);
  if (node >= NNODES) return;
  const int lane = threadIdx.x & 31;
  const int beg = g_indptr[node];
  const int end = g_indptr[node + 1];
  float ax0 = 0.f, ay0 = 0.f, ax1 = 0.f, ay1 = 0.f;
  int e = beg;
  for (; e + 3 < end; e += 4) {
    int s0 = g_csc_src[e],     s1 = g_csc_src[e + 1];
    int s2 = g_csc_src[e + 2], s3 = g_csc_src[e + 3];
    float2 v0 = __half22float2(h[(size_t)s0 * 32 + lane]);
    float2 v1 = __half22float2(h[(size_t)s1 * 32 + lane]);
    float2 v2 = __half22float2(h[(size_t)s2 * 32 + lane]);
    float2 v3 = __half22float2(h[(size_t)s3 * 32 + lane]);
    ax0 += v0.x; ay0 += v0.y; ax1 += v1.x; ay1 += v1.y;
    ax0 += v2.x; ay0 += v2.y; ax1 += v3.x; ay1 += v3.y;
  }
  for (; e < end; e++) {
    int s = g_csc_src[e];
    float2 v = __half22float2(h[(size_t)s * 32 + lane]);
    ax0 += v.x; ay0 += v.y;
  }
  float2 vs = __half22float2(h[(size_t)node * 32 + lane]);
  float di = g_dinv[node];
  float vx = (ax0 + ax1 + vs.x) * di;
  float vy = (ay0 + ay1 + vs.y) * di;
  const int c = lane * 2;
  if (MODE == 1) {
    uint32_t i0 = (uint32_t)node * HID1 + c;
    vx = drop_tanh(vx, bias[c],     i0,     k0, k1) * di;
    vy = drop_tanh(vy, bias[c + 1], i0 + 1, k0, k1) * di;
    ((__half2*)out_)[(size_t)node * 32 + lane] = __floats2half2_rn(vx, vy);
  } else {
    *(float2*)&((float*)out_)[(long)node * HID1 + c] = make_float2(vx, vy);
  }
}

// ---------------- launch ------------------------------------------------------
extern "C" void kernel_launch(void* const* d_in, const int* in_sizes, int n_in,
                              void* d_out, int out_size) {
  const float* x  = (const float*)d_in[0];
  const int*   ei = (const int*)d_in[1];
  const float* W1 = (const float*)d_in[2];
  const float* b1 = (const float*)d_in[3];
  const float* W2 = (const float*)d_in[4];
  const float* b2 = (const float*)d_in[5];
  const float* Wl = (const float*)d_in[6];
  const float* bl = (const float*)d_in[7];
  float* out = (float*)d_out;

  uint32_t a0, a1, c0, c1;
  threefry2x32(0u, 42u, 0u, 0u, a0, a1);  // dk1
  threefry2x32(0u, 42u, 0u, 1u, c0, c1);  // dk2

  void *p_hp1h, *p_h1ph, *p_agg2, *p_h2;
  cudaGetSymbolAddress(&p_hp1h, g_hp1h);
  cudaGetSymbolAddress(&p_h1ph, g_h1ph);
  cudaGetSymbolAddress(&p_agg2, g_agg2);
  cudaGetSymbolAddress(&p_h2,   g_h2);

  // ---- CSC build
  zero_deg_kernel  <<<(NNODES + 255) / 256, 256>>>();
  deg_count_kernel <<<(NEDGES / 2 + 255) / 256, 256>>>(ei);
  reduce_deg_kernel<<<NBLK, 256>>>();
  scan_bsum_kernel <<<1, 256>>>();
  finalize_kernel  <<<NBLK, 256>>>();
  csc_fill_kernel  <<<(NEDGES / 2 + 255) / 256, 256>>>(ei);

  // ---- layer 1
  gemm_tiled<DFEAT, HID1, 2><<<(NNODES + 63) / 64, 256>>>(
      x, W1, nullptr, p_hp1h, 0u, 0u);
  gather64_kernel<1><<<(NNODES + 7) / 8, 256>>>(
      (const __half2*)p_hp1h, b1, p_h1ph, a0, a1);

  // ---- layer 2
  gather64_kernel<0><<<(NNODES + 7) / 8, 256>>>(
      (const __half2*)p_h1ph, nullptr, p_agg2, 0u, 0u);
  gemm_tiled<HID1, HID2, 1><<<(NNODES + 63) / 64, 512>>>(
      (const float*)p_agg2, W2, b2, p_h2, c0, c1);

  // ---- classifier (register-tiled)
  gemm_tiled<HID2, NCLS, 0><<<(NNODES + 63) / 64, 160>>>(
      (const float*)p_h2, Wl, bl, out, 0u, 0u);
}

// round 8
// speedup vs baseline: 3.1590x; 1.0146x over previous
#include <cuda_runtime.h>
#include <cuda_fp16.h>
#include <cstdint>

#define NNODES 50000
#define NEDGES 1600000
#define DFEAT  128
#define HID1   64
#define HID2   128
#define NCLS   40
#define NBLK   196   // ceil(NNODES / 256)

// ---------------- scratch (static device globals; no runtime alloc) ----------
__device__ __align__(16) __half2 g_hp1h[(size_t)NNODES * (HID1 / 2)]; // x@W1 (raw)
__device__ __align__(16) __half2 g_h1ph[(size_t)NNODES * (HID1 / 2)]; // layer1 out, prescaled
__device__ __align__(16) float   g_agg2[(size_t)NNODES * HID1];       // A @ h1
__device__ __align__(16) float   g_h2  [(size_t)NNODES * HID2];       // layer2 out
__device__ int   g_deg   [NNODES];
__device__ float g_dinv  [NNODES];
__device__ int   g_indptr[NNODES + 1];
__device__ int   g_cursor[NNODES];
__device__ int   g_csc_src[NEDGES];
__device__ int   g_bsum[NBLK];
__device__ int   g_boff[NBLK];

// ---------------- threefry2x32 (bit-exact JAX replica) -----------------------
__host__ __device__ __forceinline__ void threefry2x32(
    uint32_t k0, uint32_t k1, uint32_t x0, uint32_t x1,
    uint32_t& o0, uint32_t& o1) {
  uint32_t ks0 = k0, ks1 = k1, ks2 = k0 ^ k1 ^ 0x1BD11BDAu;
  x0 += ks0; x1 += ks1;
#define TF_ROT(v, d) (((v) << (d)) | ((v) >> (32 - (d))))
#define TF_RND(r) { x0 += x1; x1 = TF_ROT(x1, r); x1 ^= x0; }
  TF_RND(13) TF_RND(15) TF_RND(26) TF_RND(6)
  x0 += ks1; x1 += ks2 + 1u;
  TF_RND(17) TF_RND(29) TF_RND(16) TF_RND(24)
  x0 += ks2; x1 += ks0 + 2u;
  TF_RND(13) TF_RND(15) TF_RND(26) TF_RND(6)
  x0 += ks0; x1 += ks1 + 3u;
  TF_RND(17) TF_RND(29) TF_RND(16) TF_RND(24)
  x0 += ks1; x1 += ks2 + 4u;
  TF_RND(13) TF_RND(15) TF_RND(26) TF_RND(6)
  x0 += ks2; x1 += ks0 + 5u;
#undef TF_RND
#undef TF_ROT
  o0 = x0; o1 = x1;
}

__device__ __forceinline__ float drop_tanh(float v, float b, uint32_t i,
                                           uint32_t k0, uint32_t k1) {
  uint32_t o0, o1;
  threefry2x32(k0, k1, 0u, i, o0, o1);
  uint32_t bits = o0 ^ o1;
  float u = __uint_as_float((bits >> 9) | 0x3f800000u) - 1.0f;
  float t = tanhf(v + b);
  return (u < 0.7f) ? (t * (1.0f / 0.7f)) : 0.0f;
}

// ---------------- degree + parallel scan + csc build -------------------------
__global__ void zero_deg_kernel() {
  int i = blockIdx.x * blockDim.x + threadIdx.x;
  if (i < NNODES) g_deg[i] = 0;
}

__global__ void deg_count_kernel(const int* __restrict__ eidx) {   // 2 edges/thr
  int e2 = blockIdx.x * blockDim.x + threadIdx.x;
  int e = e2 * 2;
  if (e < NEDGES) {
    int2 d = *(const int2*)&eidx[NEDGES + e];
    if ((unsigned)d.x < NNODES) atomicAdd(&g_deg[d.x], 1);
    if ((unsigned)d.y < NNODES) atomicAdd(&g_deg[d.y], 1);
  }
}

__global__ void reduce_deg_kernel() {   // grid NBLK, block 256
  __shared__ int sdata[256];
  int i = blockIdx.x * 256 + threadIdx.x;
  sdata[threadIdx.x] = (i < NNODES) ? g_deg[i] : 0;
  __syncthreads();
  for (int s = 128; s > 0; s >>= 1) {
    if (threadIdx.x < s) sdata[threadIdx.x] += sdata[threadIdx.x + s];
    __syncthreads();
  }
  if (threadIdx.x == 0) g_bsum[blockIdx.x] = sdata[0];
}

__global__ void scan_bsum_kernel() {    // 1 block, 256 threads
  const int tid = threadIdx.x, lane = tid & 31, w = tid >> 5;
  __shared__ int ws[9];
  int v = (tid < NBLK) ? g_bsum[tid] : 0;
  int x = v;
#pragma unroll
  for (int o = 1; o < 32; o <<= 1) {
    int t = __shfl_up_sync(0xffffffffu, x, o);
    if (lane >= o) x += t;
  }
  if (lane == 31) ws[w] = x;
  __syncthreads();
  if (tid == 0) {
    int run = 0;
    for (int j = 0; j < 8; j++) { int t = ws[j]; ws[j] = run; run += t; }
    ws[8] = run;
  }
  __syncthreads();
  if (tid < NBLK) g_boff[tid] = x - v + ws[w];
  if (tid == 0) g_indptr[NNODES] = ws[8];
}

__global__ void finalize_kernel() {     // grid NBLK: indptr+cursor+dinv
  const int tid = threadIdx.x, lane = tid & 31, w = tid >> 5;
  __shared__ int ws[8];
  int i = blockIdx.x * 256 + tid;
  int v = (i < NNODES) ? g_deg[i] : 0;
  int x = v;
#pragma unroll
  for (int o = 1; o < 32; o <<= 1) {
    int t = __shfl_up_sync(0xffffffffu, x, o);
    if (lane >= o) x += t;
  }
  if (lane == 31) ws[w] = x;
  __syncthreads();
  if (tid == 0) {
    int run = 0;
    for (int j = 0; j < 8; j++) { int t = ws[j]; ws[j] = run; run += t; }
  }
  __syncthreads();
  if (i < NNODES) {
    int excl = g_boff[blockIdx.x] + ws[w] + x - v;
    g_indptr[i] = excl;
    g_cursor[i] = excl;
    g_dinv[i] = rsqrtf((float)(v + 1));
  }
}

__global__ void csc_fill_kernel(const int* __restrict__ eidx) {   // 2 edges/thr
  int e2 = blockIdx.x * blockDim.x + threadIdx.x;
  int e = e2 * 2;
  if (e < NEDGES) {
    int2 s = *(const int2*)&eidx[e];
    int2 d = *(const int2*)&eidx[NEDGES + e];
    if ((unsigned)s.x < NNODES && (unsigned)d.x < NNODES) {
      int pos = atomicAdd(&g_cursor[d.x], 1);
      g_csc_src[pos] = s.x;
    }
    if ((unsigned)s.y < NNODES && (unsigned)d.y < NNODES) {
      int pos = atomicAdd(&g_cursor[d.y], 1);
      g_csc_src[pos] = s.y;
    }
  }
}

// ---------------- register-tiled GEMM (BM=64, 4x4 per thread) ----------------
// MODE 0: +bias (if non-null), float out
// MODE 1: +bias, tanh+dropout, float out
// MODE 3: raw half2 out (no dinv — keeps GEMM independent of CSC chain)
template <int K, int NC, int MODE>
__global__ __launch_bounds__(16 * (NC / 4))
void gemm_tiled(const float* __restrict__ A, const float* __restrict__ W,
                const float* __restrict__ bias, void* __restrict__ out_,
                uint32_t k0, uint32_t k1) {
  constexpr int NT = 16 * (NC / 4);
  __shared__ float As[64 * 64];
  __shared__ float Ws[64 * NC];
  const int tid = threadIdx.x;
  const int row0 = blockIdx.x * 64;
  const int mg = tid / (NC / 4);
  const int ng = tid % (NC / 4);
  const int m0 = mg * 4, c4 = ng * 4;
  float4 bv = make_float4(0.f, 0.f, 0.f, 0.f);
  if ((MODE == 0 || MODE == 1) && bias) bv = *(const float4*)&bias[c4];
  float4 acc[4] = {bv, bv, bv, bv};

  for (int kt = 0; kt < K; kt += 64) {
#pragma unroll 2
    for (int t = tid; t < 64 * 16; t += NT) {
      int r = t / 16, kk4 = (t % 16) * 4;
      int gr = row0 + r;
      float4 val = (gr < NNODES) ? *(const float4*)&A[(long)gr * K + kt + kk4]
                                 : make_float4(0.f, 0.f, 0.f, 0.f);
      *(float4*)&As[r * 64 + kk4] = val;
    }
    for (int t = tid; t < 64 * (NC / 4); t += NT) {
      int kk = t / (NC / 4), cc4 = (t % (NC / 4)) * 4;
      *(float4*)&Ws[kk * NC + cc4] = *(const float4*)&W[(long)(kt + kk) * NC + cc4];
    }
    __syncthreads();
#pragma unroll 8
    for (int kk = 0; kk < 64; kk++) {
      float a0 = As[(m0 + 0) * 64 + kk];
      float a1 = As[(m0 + 1) * 64 + kk];
      float a2 = As[(m0 + 2) * 64 + kk];
      float a3 = As[(m0 + 3) * 64 + kk];
      float4 wv = *(const float4*)&Ws[kk * NC + c4];
      acc[0].x = fmaf(a0, wv.x, acc[0].x); acc[0].y = fmaf(a0, wv.y, acc[0].y);
      acc[0].z = fmaf(a0, wv.z, acc[0].z); acc[0].w = fmaf(a0, wv.w, acc[0].w);
      acc[1].x = fmaf(a1, wv.x, acc[1].x); acc[1].y = fmaf(a1, wv.y, acc[1].y);
      acc[1].z = fmaf(a1, wv.z, acc[1].z); acc[1].w = fmaf(a1, wv.w, acc[1].w);
      acc[2].x = fmaf(a2, wv.x, acc[2].x); acc[2].y = fmaf(a2, wv.y, acc[2].y);
      acc[2].z = fmaf(a2, wv.z, acc[2].z); acc[2].w = fmaf(a2, wv.w, acc[2].w);
      acc[3].x = fmaf(a3, wv.x, acc[3].x); acc[3].y = fmaf(a3, wv.y, acc[3].y);
      acc[3].z = fmaf(a3, wv.z, acc[3].z); acc[3].w = fmaf(a3, wv.w, acc[3].w);
    }
    __syncthreads();
  }
#pragma unroll
  for (int i = 0; i < 4; i++) {
    int gr = row0 + m0 + i;
    if (gr >= NNODES) continue;
    float4 r = acc[i];
    if (MODE == 3) {
      __half2 p0 = __floats2half2_rn(r.x, r.y);
      __half2 p1 = __floats2half2_rn(r.z, r.w);
      __half2* oh = (__half2*)out_;
      uint32_t u0 = *reinterpret_cast<uint32_t*>(&p0);
      uint32_t u1 = *reinterpret_cast<uint32_t*>(&p1);
      *reinterpret_cast<uint2*>(&oh[(size_t)gr * (NC / 2) + (c4 >> 1)]) =
          make_uint2(u0, u1);
    } else {
      if (MODE == 1) {
        uint32_t i0 = (uint32_t)gr * NC + c4;
        r.x = drop_tanh(r.x, 0.f, i0,     k0, k1);
        r.y = drop_tanh(r.y, 0.f, i0 + 1, k0, k1);
        r.z = drop_tanh(r.z, 0.f, i0 + 2, k0, k1);
        r.w = drop_tanh(r.w, 0.f, i0 + 3, k0, k1);
      }
      *(float4*)&((float*)out_)[(long)gr * NC + c4] = r;
    }
  }
}

// ---------------- pull aggregation (H=64 fp16 in, warp per node) -------------
// MODE 1 (raw input): acc = sum_in dinv[s]*h[s] + dinv[d]*h[d];
//                     out_h = half( drop_tanh(acc*dinv[d] + b) * dinv[d] )
// MODE 0 (prescaled): acc = sum_in h[s] + h[d]; out_f = acc * dinv[d]
template <int MODE>
__global__ void gather64_kernel(const __half2* __restrict__ h,
                                const float* __restrict__ bias,
                                void* __restrict__ out_,
                                uint32_t k0, uint32_t k1) {
  const int node = blockIdx.x * (blockDim.x >> 5) + (threadIdx.x >> 5);
  if (node >= NNODES) return;
  const int lane = threadIdx.x & 31;
  const int beg = g_indptr[node];
  const int end = g_indptr[node + 1];
  float ax0 = 0.f, ay0 = 0.f, ax1 = 0.f, ay1 = 0.f;
  int e = beg;
  for (; e + 3 < end; e += 4) {
    int s0 = g_csc_src[e],     s1 = g_csc_src[e + 1];
    int s2 = g_csc_src[e + 2], s3 = g_csc_src[e + 3];
    float2 v0 = __half22float2(h[(size_t)s0 * 32 + lane]);
    float2 v1 = __half22float2(h[(size_t)s1 * 32 + lane]);
    float2 v2 = __half22float2(h[(size_t)s2 * 32 + lane]);
    float2 v3 = __half22float2(h[(size_t)s3 * 32 + lane]);
    if (MODE == 1) {
      float w0 = g_dinv[s0], w1 = g_dinv[s1], w2 = g_dinv[s2], w3 = g_dinv[s3];
      ax0 = fmaf(v0.x, w0, ax0); ay0 = fmaf(v0.y, w0, ay0);
      ax1 = fmaf(v1.x, w1, ax1); ay1 = fmaf(v1.y, w1, ay1);
      ax0 = fmaf(v2.x, w2, ax0); ay0 = fmaf(v2.y, w2, ay0);
      ax1 = fmaf(v3.x, w3, ax1); ay1 = fmaf(v3.y, w3, ay1);
    } else {
      ax0 += v0.x; ay0 += v0.y; ax1 += v1.x; ay1 += v1.y;
      ax0 += v2.x; ay0 += v2.y; ax1 += v3.x; ay1 += v3.y;
    }
  }
  for (; e < end; e++) {
    int s = g_csc_src[e];
    float2 v = __half22float2(h[(size_t)s * 32 + lane]);
    if (MODE == 1) {
      float w = g_dinv[s];
      ax0 = fmaf(v.x, w, ax0); ay0 = fmaf(v.y, w, ay0);
    } else {
      ax0 += v.x; ay0 += v.y;
    }
  }
  float2 vs = __half22float2(h[(size_t)node * 32 + lane]);
  float di = g_dinv[node];
  float sx, sy;
  if (MODE == 1) { sx = ax0 + ax1 + vs.x * di; sy = ay0 + ay1 + vs.y * di; }
  else           { sx = ax0 + ax1 + vs.x;      sy = ay0 + ay1 + vs.y; }
  float vx = sx * di, vy = sy * di;
  const int c = lane * 2;
  if (MODE == 1) {
    uint32_t i0 = (uint32_t)node * HID1 + c;
    vx = drop_tanh(vx, bias[c],     i0,     k0, k1) * di;
    vy = drop_tanh(vy, bias[c + 1], i0 + 1, k0, k1) * di;
    ((__half2*)out_)[(size_t)node * 32 + lane] = __floats2half2_rn(vx, vy);
  } else {
    *(float2*)&((float*)out_)[(long)node * HID1 + c] = make_float2(vx, vy);
  }
}

// ---------------- launch ------------------------------------------------------
extern "C" void kernel_launch(void* const* d_in, const int* in_sizes, int n_in,
                              void* d_out, int out_size) {
  const float* x  = (const float*)d_in[0];
  const int*   ei = (const int*)d_in[1];
  const float* W1 = (const float*)d_in[2];
  const float* b1 = (const float*)d_in[3];
  const float* W2 = (const float*)d_in[4];
  const float* b2 = (const float*)d_in[5];
  const float* Wl = (const float*)d_in[6];
  const float* bl = (const float*)d_in[7];
  float* out = (float*)d_out;

  uint32_t a0, a1, c0, c1;
  threefry2x32(0u, 42u, 0u, 0u, a0, a1);  // dk1
  threefry2x32(0u, 42u, 0u, 1u, c0, c1);  // dk2

  void *p_hp1h, *p_h1ph, *p_agg2, *p_h2;
  cudaGetSymbolAddress(&p_hp1h, g_hp1h);
  cudaGetSymbolAddress(&p_h1ph, g_h1ph);
  cudaGetSymbolAddress(&p_agg2, g_agg2);
  cudaGetSymbolAddress(&p_h2,   g_h2);

  // one-time resources (created on the pre-capture correctness call)
  static cudaStream_t s_side = nullptr;
  static cudaEvent_t ev_fork = nullptr, ev_join = nullptr;
  if (s_side == nullptr || ev_fork == nullptr || ev_join == nullptr) {
    if (s_side == nullptr) cudaStreamCreateWithFlags(&s_side, cudaStreamNonBlocking);
    if (ev_fork == nullptr) cudaEventCreateWithFlags(&ev_fork, cudaEventDisableTiming);
    if (ev_join == nullptr) cudaEventCreateWithFlags(&ev_join, cudaEventDisableTiming);
  }

  // ---- fork: CSC build chain on side stream, GEMM1 on main stream ----------
  cudaEventRecord(ev_fork, 0);
  cudaStreamWaitEvent(s_side, ev_fork, 0);

  zero_deg_kernel  <<<(NNODES + 255) / 256, 256, 0, s_side>>>();
  deg_count_kernel <<<(NEDGES / 2 + 255) / 256, 256, 0, s_side>>>(ei);
  reduce_deg_kernel<<<NBLK, 256, 0, s_side>>>();
  scan_bsum_kernel <<<1, 256, 0, s_side>>>();
  finalize_kernel  <<<NBLK, 256, 0, s_side>>>();
  csc_fill_kernel  <<<(NEDGES / 2 + 255) / 256, 256, 0, s_side>>>(ei);
  cudaEventRecord(ev_join, s_side);

  // main stream: GEMM1 (raw x@W1, fp16 out — no dinv dependency)
  gemm_tiled<DFEAT, HID1, 3><<<(NNODES + 63) / 64, 256>>>(
      x, W1, nullptr, p_hp1h, 0u, 0u);

  // ---- join, then the dependent chain --------------------------------------
  cudaStreamWaitEvent(0, ev_join, 0);

  gather64_kernel<1><<<(NNODES + 7) / 8, 256>>>(
      (const __half2*)p_hp1h, b1, p_h1ph, a0, a1);
  gather64_kernel<0><<<(NNODES + 7) / 8, 256>>>(
      (const __half2*)p_h1ph, nullptr, p_agg2, 0u, 0u);
  gemm_tiled<HID1, HID2, 1><<<(NNODES + 63) / 64, 512>>>(
      (const float*)p_agg2, W2, b2, p_h2, c0, c1);
  gemm_tiled<HID2, NCLS, 0><<<(NNODES + 63) / 64, 160>>>(
      (const float*)p_h2, Wl, bl, out, 0u, 0u);
}